// round 2
// baseline (speedup 1.0000x reference)
#include <cuda_runtime.h>
#include <math.h>
#include <stdint.h>

// Problem constants
#define BB 4
#define TT 1024
#define DD 1024
#define HH 16
#define HDIM 64
#define LL 8
#define VV 50257
#define ROWS (BB*TT)            // 4096
#define SCALE_ATT 0.07216878364870322f  // 1/sqrt(3*1024/16) = 1/sqrt(192)

// ---------------------------------------------------------------------------
// Scratch (static device globals; no runtime allocation)
// ---------------------------------------------------------------------------
__device__ float g_x   [ (size_t)ROWS * DD     ];   // residual stream
__device__ float g_h   [ (size_t)ROWS * DD     ];   // layernorm output
__device__ float g_qkv [ (size_t)ROWS * 3 * DD ];   // qkv
__device__ float g_y   [ (size_t)ROWS * DD     ];   // attention output
__device__ float g_m   [ (size_t)ROWS * 4 * DD ];   // mlp hidden
__device__ float g_nll [ ROWS ];                    // per-token masked nll

// ---------------------------------------------------------------------------
// Embedding: x = tok_emb[idx] + pos_emb[t]
// ---------------------------------------------------------------------------
__global__ __launch_bounds__(256) void embed_kernel(
    const int* __restrict__ idx, const float* __restrict__ tok,
    const float* __restrict__ pos, float* __restrict__ x)
{
    int row = blockIdx.x;            // 0..4095
    int t   = row & (TT - 1);
    int id  = idx[row];
    const float4* tp = (const float4*)(tok + (size_t)id * DD);
    const float4* pp = (const float4*)(pos + (size_t)t  * DD);
    float4*       xp = (float4*)(x + (size_t)row * DD);
    int i = threadIdx.x;             // DD/4 = 256
    float4 a = tp[i], b = pp[i];
    a.x += b.x; a.y += b.y; a.z += b.z; a.w += b.w;
    xp[i] = a;
}

// ---------------------------------------------------------------------------
// LayerNorm over D=1024, one block per row, 256 threads (4 elems/thread)
// ---------------------------------------------------------------------------
__global__ __launch_bounds__(256) void ln_kernel(
    const float* __restrict__ x, const float* __restrict__ g,
    const float* __restrict__ b, float* __restrict__ out)
{
    __shared__ float s1[256];
    __shared__ float s2[256];
    int row = blockIdx.x;
    int tid = threadIdx.x;
    float4 v = ((const float4*)(x + (size_t)row * DD))[tid];
    float s  = v.x + v.y + v.z + v.w;
    float ss = v.x*v.x + v.y*v.y + v.z*v.z + v.w*v.w;
    s1[tid] = s; s2[tid] = ss;
    __syncthreads();
    for (int o = 128; o > 0; o >>= 1) {
        if (tid < o) { s1[tid] += s1[tid+o]; s2[tid] += s2[tid+o]; }
        __syncthreads();
    }
    float mu   = s1[0] * (1.0f / DD);
    float var  = s2[0] * (1.0f / DD) - mu * mu;
    float rstd = rsqrtf(var + 1e-5f);
    float4 gv = ((const float4*)g)[tid];
    float4 bv = ((const float4*)b)[tid];
    float4 o4;
    o4.x = (v.x - mu) * rstd * gv.x + bv.x;
    o4.y = (v.y - mu) * rstd * gv.y + bv.y;
    o4.z = (v.z - mu) * rstd * gv.z + bv.z;
    o4.w = (v.w - mu) * rstd * gv.w + bv.w;
    ((float4*)(out + (size_t)row * DD))[tid] = o4;
}

// ---------------------------------------------------------------------------
// SGEMM: C[M,N] = A[M,K] @ B[K,N] (+bias) (+relu / +residual)
// BM=128 BN=128 BK=8, 256 threads, 8x8 per-thread microtile.
// M is always a multiple of 128; N may be ragged AND unaligned (LM head,
// N=50257 odd -> B rows are not 16B aligned; use scalar loads then).
// EPI: 0 = bias, 1 = bias+relu, 2 = bias+residual
// ---------------------------------------------------------------------------
template<int EPI>
__global__ __launch_bounds__(256) void sgemm_kernel(
    int M, int N, int K,
    const float* __restrict__ A, const float* __restrict__ B,
    const float* __restrict__ bias, const float* __restrict__ res,
    float* __restrict__ C)
{
    constexpr int BM = 128, BN = 128, BK = 8, TM = 8, TN = 8;
    __shared__ float As[BK][BM];
    __shared__ float Bs[BK][BN];

    const int tid   = threadIdx.x;
    const int nbase = blockIdx.x * BN;
    const int mbase = blockIdx.y * BM;

    // A-tile load mapping: 128 rows x 8 cols, float4 along K
    const int arow = tid >> 1;           // 0..127
    const int acol = (tid & 1) << 2;     // 0 or 4
    // B-tile load mapping: 8 rows x 128 cols, float4 along N
    const int brow = tid >> 5;           // 0..7
    const int bcol = (tid & 31) << 2;    // 0..124

    // compute mapping: 16x16 thread grid, each 8x8
    const int tr = (tid >> 4) * TM;
    const int tc = (tid & 15) * TN;

    // vectorized B loads require tile fully in-bounds AND 16B-aligned rows
    const bool b_vec = ((N & 3) == 0) && (nbase + BN <= N);

    float acc[TM][TN];
    #pragma unroll
    for (int i = 0; i < TM; i++)
        #pragma unroll
        for (int j = 0; j < TN; j++) acc[i][j] = 0.0f;

    const float* Ap = A + (size_t)mbase * K;

    for (int k0 = 0; k0 < K; k0 += BK) {
        // load A tile (always in-bounds, K % 4 == 0 always here)
        float4 av = *reinterpret_cast<const float4*>(Ap + (size_t)arow * K + k0 + acol);
        As[acol+0][arow] = av.x;
        As[acol+1][arow] = av.y;
        As[acol+2][arow] = av.z;
        As[acol+3][arow] = av.w;
        // load B tile
        int gcol = nbase + bcol;
        float4 bv;
        if (b_vec) {
            bv = *reinterpret_cast<const float4*>(B + (size_t)(k0 + brow) * N + gcol);
        } else {
            const float* bp = B + (size_t)(k0 + brow) * N;
            bv.x = (gcol + 0 < N) ? __ldg(bp + gcol + 0) : 0.0f;
            bv.y = (gcol + 1 < N) ? __ldg(bp + gcol + 1) : 0.0f;
            bv.z = (gcol + 2 < N) ? __ldg(bp + gcol + 2) : 0.0f;
            bv.w = (gcol + 3 < N) ? __ldg(bp + gcol + 3) : 0.0f;
        }
        *reinterpret_cast<float4*>(&Bs[brow][bcol]) = bv;
        __syncthreads();

        #pragma unroll
        for (int kk = 0; kk < BK; kk++) {
            float ar[TM], br[TN];
            #pragma unroll
            for (int i = 0; i < TM; i++) ar[i] = As[kk][tr + i];
            #pragma unroll
            for (int j = 0; j < TN; j++) br[j] = Bs[kk][tc + j];
            #pragma unroll
            for (int i = 0; i < TM; i++)
                #pragma unroll
                for (int j = 0; j < TN; j++)
                    acc[i][j] += ar[i] * br[j];
        }
        __syncthreads();
    }

    // epilogue (scalar stores; safe for any N)
    #pragma unroll
    for (int i = 0; i < TM; i++) {
        int row = mbase + tr + i;
        float* crow = C + (size_t)row * N;
        const float* rrow = (EPI == 2) ? (res + (size_t)row * N) : nullptr;
        #pragma unroll
        for (int j = 0; j < TN; j++) {
            int col = nbase + tc + j;
            if (col < N) {
                float v = acc[i][j];
                if (bias != nullptr) v += bias[col];
                if (EPI == 1) v = fmaxf(v, 0.0f);
                if (EPI == 2) v += rrow[col];
                crow[col] = v;
            }
        }
    }
}

// ---------------------------------------------------------------------------
// Fused causal attention. One thread per query (q + acc in registers),
// K/V staged 64 keys at a time in shared memory, online softmax.
// Grid: (B*H, T/128), block: 128 threads.
// ---------------------------------------------------------------------------
__global__ __launch_bounds__(128) void attn_kernel(
    const float* __restrict__ qkv, float* __restrict__ y)
{
    const int bh = blockIdx.x;               // b*H + h
    const int b  = bh >> 4;
    const int h  = bh & (HH - 1);
    const int t  = blockIdx.y * 128 + threadIdx.x;   // query position
    const int row = b * TT + t;

    __shared__ float Kt[64][HDIM];
    __shared__ float Vt[64][HDIM];

    // load q into registers
    float4 qv[16];
    {
        const float4* qp = (const float4*)(qkv + (size_t)row * (3*DD) + h * HDIM);
        #pragma unroll
        for (int i = 0; i < 16; i++) qv[i] = qp[i];
    }

    float4 acc[16];
    #pragma unroll
    for (int i = 0; i < 16; i++) acc[i] = make_float4(0.f, 0.f, 0.f, 0.f);
    float m = -1e30f, l = 0.0f;

    const int kmax = blockIdx.y * 128 + 127;   // largest key any thread needs

    for (int k0 = 0; k0 <= kmax; k0 += 64) {
        // cooperative load of 64 keys + values (2 threads per row, 32 floats each)
        {
            int r  = threadIdx.x >> 1;
            int c0 = (threadIdx.x & 1) * 32;
            const float* kp = qkv + (size_t)(b * TT + k0 + r) * (3*DD) + DD   + h * HDIM + c0;
            const float* vp = qkv + (size_t)(b * TT + k0 + r) * (3*DD) + 2*DD + h * HDIM + c0;
            #pragma unroll
            for (int i = 0; i < 8; i++) {
                *(float4*)&Kt[r][c0 + i*4] = *(const float4*)(kp + i*4);
                *(float4*)&Vt[r][c0 + i*4] = *(const float4*)(vp + i*4);
            }
        }
        __syncthreads();

        int jmax = t - k0;
        if (jmax > 63) jmax = 63;
        for (int j = 0; j <= jmax; j++) {
            const float4* kr = (const float4*)&Kt[j][0];
            float s = 0.0f;
            #pragma unroll
            for (int i = 0; i < 16; i++) {
                float4 kk = kr[i];
                s += qv[i].x*kk.x + qv[i].y*kk.y + qv[i].z*kk.z + qv[i].w*kk.w;
            }
            s *= SCALE_ATT;
            const float4* vr = (const float4*)&Vt[j][0];
            if (s <= m) {
                float p = __expf(s - m);
                l += p;
                #pragma unroll
                for (int i = 0; i < 16; i++) {
                    float4 vv = vr[i];
                    acc[i].x += p * vv.x; acc[i].y += p * vv.y;
                    acc[i].z += p * vv.z; acc[i].w += p * vv.w;
                }
            } else {
                float c = __expf(m - s);
                m = s;
                l = l * c + 1.0f;
                #pragma unroll
                for (int i = 0; i < 16; i++) {
                    float4 vv = vr[i];
                    acc[i].x = acc[i].x * c + vv.x; acc[i].y = acc[i].y * c + vv.y;
                    acc[i].z = acc[i].z * c + vv.z; acc[i].w = acc[i].w * c + vv.w;
                }
            }
        }
        __syncthreads();
    }

    float inv = 1.0f / l;
    float4* yp = (float4*)(y + (size_t)row * DD + h * HDIM);
    #pragma unroll
    for (int i = 0; i < 16; i++) {
        float4 o;
        o.x = acc[i].x * inv; o.y = acc[i].y * inv;
        o.z = acc[i].z * inv; o.w = acc[i].w * inv;
        yp[i] = o;
    }
}

// ---------------------------------------------------------------------------
// Per-row log-softmax NLL over V=50257 (two passes over the row)
// ---------------------------------------------------------------------------
__global__ __launch_bounds__(256) void nll_kernel(
    const float* __restrict__ logits, const int* __restrict__ tgt,
    float* __restrict__ nll)
{
    __shared__ float red[256];
    int row = blockIdx.x;
    int tid = threadIdx.x;
    const float* lr = logits + (size_t)row * VV;

    float mx = -3.4e38f;
    for (int i = tid; i < VV; i += 256) mx = fmaxf(mx, lr[i]);
    red[tid] = mx; __syncthreads();
    for (int o = 128; o > 0; o >>= 1) {
        if (tid < o) red[tid] = fmaxf(red[tid], red[tid + o]);
        __syncthreads();
    }
    mx = red[0];
    __syncthreads();

    float s = 0.0f;
    for (int i = tid; i < VV; i += 256) s += __expf(lr[i] - mx);
    red[tid] = s; __syncthreads();
    for (int o = 128; o > 0; o >>= 1) {
        if (tid < o) red[tid] += red[tid + o];
        __syncthreads();
    }
    if (tid == 0) {
        float lse = mx + logf(red[0]);
        int tg = tgt[row];
        nll[row] = (tg != 0) ? (lse - lr[tg]) : 0.0f;
    }
}

// Deterministic final reduction: loss = sum(nll) / max(count, 1)
__global__ __launch_bounds__(256) void loss_kernel(
    const float* __restrict__ nll, const int* __restrict__ tgt,
    float* __restrict__ out)
{
    __shared__ float s[256];
    __shared__ float c[256];
    int tid = threadIdx.x;
    float sv = 0.0f, cv = 0.0f;
    for (int i = tid; i < ROWS; i += 256) {
        sv += nll[i];
        cv += (tgt[i] != 0) ? 1.0f : 0.0f;
    }
    s[tid] = sv; c[tid] = cv; __syncthreads();
    for (int o = 128; o > 0; o >>= 1) {
        if (tid < o) { s[tid] += s[tid+o]; c[tid] += c[tid+o]; }
        __syncthreads();
    }
    if (tid == 0) out[0] = s[0] / fmaxf(c[0], 1.0f);
}

// ---------------------------------------------------------------------------
// Launcher
// ---------------------------------------------------------------------------
extern "C" void kernel_launch(void* const* d_in, const int* in_sizes, int n_in,
                              void* d_out, int out_size)
{
    const int*   idx   = (const int*)  d_in[0];
    const int*   tgt   = (const int*)  d_in[1];
    const float* tok   = (const float*)d_in[2];
    const float* pos   = (const float*)d_in[3];
    const float* ln1g  = (const float*)d_in[4];
    const float* ln1b  = (const float*)d_in[5];
    const float* wqkv  = (const float*)d_in[6];
    const float* bqkv  = (const float*)d_in[7];
    const float* wproj = (const float*)d_in[8];
    const float* bproj = (const float*)d_in[9];
    const float* ln2g  = (const float*)d_in[10];
    const float* ln2b  = (const float*)d_in[11];
    const float* w1    = (const float*)d_in[12];
    const float* b1    = (const float*)d_in[13];
    const float* w2    = (const float*)d_in[14];
    const float* b2    = (const float*)d_in[15];
    const float* lmw   = (const float*)d_in[16];

    float *px, *ph, *pqkv, *py, *pm, *pnll;
    cudaGetSymbolAddress((void**)&px,   g_x);
    cudaGetSymbolAddress((void**)&ph,   g_h);
    cudaGetSymbolAddress((void**)&pqkv, g_qkv);
    cudaGetSymbolAddress((void**)&py,   g_y);
    cudaGetSymbolAddress((void**)&pm,   g_m);
    cudaGetSymbolAddress((void**)&pnll, g_nll);

    float* out = (float*)d_out;

    embed_kernel<<<ROWS, 256>>>(idx, tok, pos, px);

    for (int l = 0; l < LL; l++) {
        // ln1
        ln_kernel<<<ROWS, 256>>>(px, ln1g + (size_t)l*DD, ln1b + (size_t)l*DD, ph);
        // qkv = h @ wqkv + bqkv
        sgemm_kernel<0><<<dim3(3*DD/128, ROWS/128), 256>>>(
            ROWS, 3*DD, DD, ph, wqkv + (size_t)l*DD*3*DD,
            bqkv + (size_t)l*3*DD, nullptr, pqkv);
        // attention
        attn_kernel<<<dim3(BB*HH, TT/128), 128>>>(pqkv, py);
        // x = x + y @ wproj + bproj
        sgemm_kernel<2><<<dim3(DD/128, ROWS/128), 256>>>(
            ROWS, DD, DD, py, wproj + (size_t)l*DD*DD,
            bproj + (size_t)l*DD, px, px);
        // ln2
        ln_kernel<<<ROWS, 256>>>(px, ln2g + (size_t)l*DD, ln2b + (size_t)l*DD, ph);
        // m = relu(h @ w1 + b1)
        sgemm_kernel<1><<<dim3(4*DD/128, ROWS/128), 256>>>(
            ROWS, 4*DD, DD, ph, w1 + (size_t)l*DD*4*DD,
            b1 + (size_t)l*4*DD, nullptr, pm);
        // x = x + m @ w2 + b2
        sgemm_kernel<2><<<dim3(DD/128, ROWS/128), 256>>>(
            ROWS, DD, 4*DD, pm, w2 + (size_t)l*4*DD*DD,
            b2 + (size_t)l*DD, px, px);
    }

    // logits = x @ lm_w  (no bias), straight into d_out
    sgemm_kernel<0><<<dim3((VV + 127)/128, ROWS/128), 256>>>(
        ROWS, VV, DD, px, lmw, nullptr, nullptr, out);

    // loss
    nll_kernel<<<ROWS, 256>>>(out, tgt, pnll);
    size_t nlog = (size_t)ROWS * VV;
    if ((size_t)out_size > nlog) {
        loss_kernel<<<1, 256>>>(pnll, tgt, out + nlog);
    }
}

// round 4
// speedup vs baseline: 2.0393x; 2.0393x over previous
#include <cuda_runtime.h>
#include <cuda_bf16.h>
#include <math.h>
#include <stdint.h>

// Problem constants
#define BB 4
#define TT 1024
#define DD 1024
#define HH 16
#define HDIM 64
#define LL 8
#define VV 50257
#define VPAD 50304
#define ROWS (BB*TT)            // 4096
#define SCALE_ATT 0.07216878364870322f  // 1/sqrt(192)

// ---------------------------------------------------------------------------
// Scratch (static device globals; no runtime allocation)
// ---------------------------------------------------------------------------
__device__ float g_x   [ (size_t)ROWS * DD     ];
__device__ float g_h   [ (size_t)ROWS * DD     ];
__device__ float g_qkv [ (size_t)ROWS * 3 * DD ];
__device__ float g_y   [ (size_t)ROWS * DD     ];
__device__ float g_m   [ (size_t)ROWS * 4 * DD ];
__device__ float g_nll [ ROWS ];
// transposed weights ([N,K] row-major so B operand is K-major / "col" for mma)
__device__ float g_wqkvT [ (size_t)LL * 3*DD * DD ];
__device__ float g_wprojT[ (size_t)LL * DD * DD ];
__device__ float g_w1T   [ (size_t)LL * 4*DD * DD ];
__device__ float g_w2T   [ (size_t)LL * DD * 4*DD ];
__device__ float g_lmwT  [ (size_t)VPAD * DD ];

// ---------------------------------------------------------------------------
// bf16 split helpers: v = hi + lo with hi,lo bf16 (error ~2^-18 relative)
// ---------------------------------------------------------------------------
__device__ __forceinline__ uint32_t pack2_hi(float x, float y, float& rx, float& ry) {
    __nv_bfloat16 hx = __float2bfloat16_rn(x);
    __nv_bfloat16 hy = __float2bfloat16_rn(y);
    rx = x - __bfloat162float(hx);
    ry = y - __bfloat162float(hy);
    return (uint32_t)__bfloat16_as_ushort(hx) | ((uint32_t)__bfloat16_as_ushort(hy) << 16);
}
__device__ __forceinline__ uint32_t pack2(float x, float y) {
    __nv_bfloat16 hx = __float2bfloat16_rn(x);
    __nv_bfloat16 hy = __float2bfloat16_rn(y);
    return (uint32_t)__bfloat16_as_ushort(hx) | ((uint32_t)__bfloat16_as_ushort(hy) << 16);
}

#define MMA_BF16(d, a, b) \
    asm volatile("mma.sync.aligned.m16n8k16.row.col.f32.bf16.bf16.f32 " \
        "{%0,%1,%2,%3}, {%4,%5,%6,%7}, {%8,%9}, {%0,%1,%2,%3};" \
        : "+f"((d)[0]), "+f"((d)[1]), "+f"((d)[2]), "+f"((d)[3]) \
        : "r"((a)[0]), "r"((a)[1]), "r"((a)[2]), "r"((a)[3]), \
          "r"((b)[0]), "r"((b)[1]))

// ---------------------------------------------------------------------------
// bf16-split tensor GEMM: C[M,N] = A[M,K] @ Bt[N,K]^T (+bias)(+relu/+res)
// CTA tile 128x128, K-chunk 32, double-buffered smem, 256 threads.
// Warp tile 64x32 (warp grid 2x4). EPI: 0=bias, 1=bias+relu, 2=bias+residual.
// smem layout per buffer: Ahi | Alo | Bhi | Blo, each 128 rows x 80 bytes
// (32 bf16 of payload + 8 pad bf16 -> conflict-free fragment loads).
// ---------------------------------------------------------------------------
#define TILEB 10240            // 128 * 80 bytes
#define BUFB  (4*TILEB)        // 40960
#define SMEM_DYN (2*BUFB)      // 81920; epilogue Cs (128*132*4=67584) fits

template<int EPI>
__global__ __launch_bounds__(256) void hgemm_kernel(
    int M, int N, int K,
    const float* __restrict__ A,    // [M,K]
    const float* __restrict__ Bt,   // [Npad,K]
    const float* __restrict__ bias,
    const float* __restrict__ res,
    float* __restrict__ C)
{
    extern __shared__ char smem[];
    const int tid  = threadIdx.x;
    const int wid  = tid >> 5;
    const int lane = tid & 31;
    const int mbase = blockIdx.y * 128;
    const int nbase = blockIdx.x * 128;
    const int warp_m = wid & 1;          // 0..1 (64 rows each)
    const int warp_n = wid >> 1;         // 0..3 (32 cols each)
    const int g = lane >> 2;             // 0..7
    const int q = lane & 3;              // 0..3

    float acc[4][4][4];
    #pragma unroll
    for (int m = 0; m < 4; m++)
        #pragma unroll
        for (int n = 0; n < 4; n++)
            #pragma unroll
            for (int r = 0; r < 4; r++) acc[m][n][r] = 0.0f;

    // prefetch chunk 0: each thread 4x float4 from A and Bt
    float4 rA[4], rB[4];
    #pragma unroll
    for (int i = 0; i < 4; i++) {
        int u = tid + i*256; int row = u >> 3, kq = u & 7;
        rA[i] = *(const float4*)(A  + (size_t)(mbase+row)*K + kq*4);
        rB[i] = *(const float4*)(Bt + (size_t)(nbase+row)*K + kq*4);
    }

    const int nch = K >> 5;

    for (int it = 0; it < nch; it++) {
        char* buf = smem + (it & 1) * BUFB;

        // split + store current chunk
        #pragma unroll
        for (int i = 0; i < 4; i++) {
            int u = tid + i*256; int row = u >> 3, kq = u & 7;
            uint32_t off = (uint32_t)row * 80 + kq * 8;
            float lx, ly, lz, lw;
            uint2 h, l;
            h.x = pack2_hi(rA[i].x, rA[i].y, lx, ly);
            h.y = pack2_hi(rA[i].z, rA[i].w, lz, lw);
            l.x = pack2(lx, ly); l.y = pack2(lz, lw);
            *(uint2*)(buf + off)          = h;   // Ahi
            *(uint2*)(buf + TILEB + off)  = l;   // Alo
            h.x = pack2_hi(rB[i].x, rB[i].y, lx, ly);
            h.y = pack2_hi(rB[i].z, rB[i].w, lz, lw);
            l.x = pack2(lx, ly); l.y = pack2(lz, lw);
            *(uint2*)(buf + 2*TILEB + off) = h;  // Bhi
            *(uint2*)(buf + 3*TILEB + off) = l;  // Blo
        }
        __syncthreads();

        // prefetch next chunk (overlaps with mma work below)
        if (it + 1 < nch) {
            int k0 = (it + 1) << 5;
            #pragma unroll
            for (int i = 0; i < 4; i++) {
                int u = tid + i*256; int row = u >> 3, kq = u & 7;
                rA[i] = *(const float4*)(A  + (size_t)(mbase+row)*K + k0 + kq*4);
                rB[i] = *(const float4*)(Bt + (size_t)(nbase+row)*K + k0 + kq*4);
            }
        }

        // compute: 2 x k16 steps
        #pragma unroll
        for (int ks = 0; ks < 32; ks += 16) {
            uint32_t ah[4][4], al[4][4];
            #pragma unroll
            for (int m = 0; m < 4; m++) {
                int row = warp_m*64 + m*16 + g;
                const char* pa = buf + (uint32_t)row*80 + (ks + 2*q)*2;
                ah[m][0] = *(const uint32_t*)(pa);
                ah[m][1] = *(const uint32_t*)(pa + 8*80);
                ah[m][2] = *(const uint32_t*)(pa + 16);
                ah[m][3] = *(const uint32_t*)(pa + 8*80 + 16);
                const char* pl = pa + TILEB;
                al[m][0] = *(const uint32_t*)(pl);
                al[m][1] = *(const uint32_t*)(pl + 8*80);
                al[m][2] = *(const uint32_t*)(pl + 16);
                al[m][3] = *(const uint32_t*)(pl + 8*80 + 16);
            }
            uint32_t bh[4][2], bl[4][2];
            #pragma unroll
            for (int n = 0; n < 4; n++) {
                int row = warp_n*32 + n*8 + g;
                const char* pb = buf + 2*TILEB + (uint32_t)row*80 + (ks + 2*q)*2;
                bh[n][0] = *(const uint32_t*)(pb);
                bh[n][1] = *(const uint32_t*)(pb + 16);
                const char* pl = pb + TILEB;
                bl[n][0] = *(const uint32_t*)(pl);
                bl[n][1] = *(const uint32_t*)(pl + 16);
            }
            #pragma unroll
            for (int m = 0; m < 4; m++)
                #pragma unroll
                for (int n = 0; n < 4; n++) {
                    MMA_BF16(acc[m][n], ah[m], bh[n]);
                    MMA_BF16(acc[m][n], ah[m], bl[n]);
                    MMA_BF16(acc[m][n], al[m], bh[n]);
                }
        }
        __syncthreads();
    }

    // epilogue: stage through smem for coalesced writes
    float* Cs = (float*)smem;   // [128][132]
    #pragma unroll
    for (int m = 0; m < 4; m++) {
        int r0 = warp_m*64 + m*16 + g;
        #pragma unroll
        for (int n = 0; n < 4; n++) {
            int col = warp_n*32 + n*8 + 2*q;
            Cs[r0*132 + col]       = acc[m][n][0];
            Cs[r0*132 + col + 1]   = acc[m][n][1];
            Cs[(r0+8)*132 + col]   = acc[m][n][2];
            Cs[(r0+8)*132 + col+1] = acc[m][n][3];
        }
    }
    __syncthreads();

    if ((N & 3) == 0) {
        #pragma unroll
        for (int i = 0; i < 16; i++) {
            int u = tid + i*256;
            int row = u >> 5, c4 = (u & 31) * 4;
            int col = nbase + c4;
            float v0 = Cs[row*132 + c4 + 0];
            float v1 = Cs[row*132 + c4 + 1];
            float v2 = Cs[row*132 + c4 + 2];
            float v3 = Cs[row*132 + c4 + 3];
            if (bias) { v0 += bias[col]; v1 += bias[col+1]; v2 += bias[col+2]; v3 += bias[col+3]; }
            if (EPI == 1) {
                v0 = fmaxf(v0, 0.f); v1 = fmaxf(v1, 0.f);
                v2 = fmaxf(v2, 0.f); v3 = fmaxf(v3, 0.f);
            }
            if (EPI == 2) {
                const float4 rv = *(const float4*)(res + (size_t)(mbase+row)*N + col);
                v0 += rv.x; v1 += rv.y; v2 += rv.z; v3 += rv.w;
            }
            *(float4*)(C + (size_t)(mbase+row)*N + col) = make_float4(v0, v1, v2, v3);
        }
    } else {
        #pragma unroll
        for (int i = 0; i < 16; i++) {
            int u = tid + i*256;
            int row = u >> 5, c4 = (u & 31) * 4;
            float* crow = C + (size_t)(mbase+row)*N;
            #pragma unroll
            for (int j = 0; j < 4; j++) {
                int col = nbase + c4 + j;
                if (col < N) {
                    float v = Cs[row*132 + c4 + j];
                    if (bias) v += bias[col];
                    if (EPI == 1) v = fmaxf(v, 0.f);
                    if (EPI == 2) v += res[(size_t)(mbase+row)*N + col];
                    crow[col] = v;
                }
            }
        }
    }
}

// ---------------------------------------------------------------------------
// Tiled transpose: in [K,N] (per layer) -> out [Npad,K], zero-pad rows >= N
// ---------------------------------------------------------------------------
__global__ __launch_bounds__(256) void tp_kernel(
    const float* __restrict__ in, float* __restrict__ out,
    int K, int N, int Npad, size_t inStride, size_t outStride)
{
    __shared__ float t[32][33];
    const float* ip = in  + blockIdx.z * inStride;
    float*       op = out + blockIdx.z * outStride;
    int n0 = blockIdx.x * 32, k0 = blockIdx.y * 32;
    int tx = threadIdx.x & 31, ty = threadIdx.x >> 5;
    #pragma unroll
    for (int j = ty; j < 32; j += 8) {
        int k = k0 + j, n = n0 + tx;
        t[j][tx] = (k < K && n < N) ? ip[(size_t)k * N + n] : 0.0f;
    }
    __syncthreads();
    #pragma unroll
    for (int j = ty; j < 32; j += 8) {
        int n = n0 + j, k = k0 + tx;
        if (n < Npad && k < K) op[(size_t)n * K + k] = t[tx][j];
    }
}

// ---------------------------------------------------------------------------
// Embedding
// ---------------------------------------------------------------------------
__global__ __launch_bounds__(256) void embed_kernel(
    const int* __restrict__ idx, const float* __restrict__ tok,
    const float* __restrict__ pos, float* __restrict__ x)
{
    int row = blockIdx.x;
    int t   = row & (TT - 1);
    int id  = idx[row];
    const float4* tp = (const float4*)(tok + (size_t)id * DD);
    const float4* pp = (const float4*)(pos + (size_t)t  * DD);
    float4*       xp = (float4*)(x + (size_t)row * DD);
    int i = threadIdx.x;
    float4 a = tp[i], b = pp[i];
    a.x += b.x; a.y += b.y; a.z += b.z; a.w += b.w;
    xp[i] = a;
}

// ---------------------------------------------------------------------------
// LayerNorm
// ---------------------------------------------------------------------------
__global__ __launch_bounds__(256) void ln_kernel(
    const float* __restrict__ x, const float* __restrict__ g,
    const float* __restrict__ b, float* __restrict__ out)
{
    __shared__ float s1[256];
    __shared__ float s2[256];
    int row = blockIdx.x;
    int tid = threadIdx.x;
    float4 v = ((const float4*)(x + (size_t)row * DD))[tid];
    float s  = v.x + v.y + v.z + v.w;
    float ss = v.x*v.x + v.y*v.y + v.z*v.z + v.w*v.w;
    s1[tid] = s; s2[tid] = ss;
    __syncthreads();
    for (int o = 128; o > 0; o >>= 1) {
        if (tid < o) { s1[tid] += s1[tid+o]; s2[tid] += s2[tid+o]; }
        __syncthreads();
    }
    float mu   = s1[0] * (1.0f / DD);
    float var  = s2[0] * (1.0f / DD) - mu * mu;
    float rstd = rsqrtf(var + 1e-5f);
    float4 gv = ((const float4*)g)[tid];
    float4 bv = ((const float4*)b)[tid];
    float4 o4;
    o4.x = (v.x - mu) * rstd * gv.x + bv.x;
    o4.y = (v.y - mu) * rstd * gv.y + bv.y;
    o4.z = (v.z - mu) * rstd * gv.z + bv.z;
    o4.w = (v.w - mu) * rstd * gv.w + bv.w;
    ((float4*)(out + (size_t)row * DD))[tid] = o4;
}

// ---------------------------------------------------------------------------
// Fused causal attention (one thread per query, online softmax)
// ---------------------------------------------------------------------------
__global__ __launch_bounds__(128) void attn_kernel(
    const float* __restrict__ qkv, float* __restrict__ y)
{
    const int bh = blockIdx.x;
    const int b  = bh >> 4;
    const int h  = bh & (HH - 1);
    const int t  = blockIdx.y * 128 + threadIdx.x;
    const int row = b * TT + t;

    __shared__ float Kt[64][HDIM];
    __shared__ float Vt[64][HDIM];

    float4 qv[16];
    {
        const float4* qp = (const float4*)(qkv + (size_t)row * (3*DD) + h * HDIM);
        #pragma unroll
        for (int i = 0; i < 16; i++) qv[i] = qp[i];
    }

    float4 acc[16];
    #pragma unroll
    for (int i = 0; i < 16; i++) acc[i] = make_float4(0.f, 0.f, 0.f, 0.f);
    float m = -1e30f, l = 0.0f;

    const int kmax = blockIdx.y * 128 + 127;

    for (int k0 = 0; k0 <= kmax; k0 += 64) {
        {
            int r  = threadIdx.x >> 1;
            int c0 = (threadIdx.x & 1) * 32;
            const float* kp = qkv + (size_t)(b * TT + k0 + r) * (3*DD) + DD   + h * HDIM + c0;
            const float* vp = qkv + (size_t)(b * TT + k0 + r) * (3*DD) + 2*DD + h * HDIM + c0;
            #pragma unroll
            for (int i = 0; i < 8; i++) {
                *(float4*)&Kt[r][c0 + i*4] = *(const float4*)(kp + i*4);
                *(float4*)&Vt[r][c0 + i*4] = *(const float4*)(vp + i*4);
            }
        }
        __syncthreads();

        int jmax = t - k0;
        if (jmax > 63) jmax = 63;
        for (int j = 0; j <= jmax; j++) {
            const float4* kr = (const float4*)&Kt[j][0];
            float s = 0.0f;
            #pragma unroll
            for (int i = 0; i < 16; i++) {
                float4 kk = kr[i];
                s += qv[i].x*kk.x + qv[i].y*kk.y + qv[i].z*kk.z + qv[i].w*kk.w;
            }
            s *= SCALE_ATT;
            const float4* vr = (const float4*)&Vt[j][0];
            if (s <= m) {
                float p = __expf(s - m);
                l += p;
                #pragma unroll
                for (int i = 0; i < 16; i++) {
                    float4 vv = vr[i];
                    acc[i].x += p * vv.x; acc[i].y += p * vv.y;
                    acc[i].z += p * vv.z; acc[i].w += p * vv.w;
                }
            } else {
                float c = __expf(m - s);
                m = s;
                l = l * c + 1.0f;
                #pragma unroll
                for (int i = 0; i < 16; i++) {
                    float4 vv = vr[i];
                    acc[i].x = acc[i].x * c + vv.x; acc[i].y = acc[i].y * c + vv.y;
                    acc[i].z = acc[i].z * c + vv.z; acc[i].w = acc[i].w * c + vv.w;
                }
            }
        }
        __syncthreads();
    }

    float inv = 1.0f / l;
    float4* yp = (float4*)(y + (size_t)row * DD + h * HDIM);
    #pragma unroll
    for (int i = 0; i < 16; i++) {
        float4 o;
        o.x = acc[i].x * inv; o.y = acc[i].y * inv;
        o.z = acc[i].z * inv; o.w = acc[i].w * inv;
        yp[i] = o;
    }
}

// ---------------------------------------------------------------------------
// NLL + loss
// ---------------------------------------------------------------------------
__global__ __launch_bounds__(256) void nll_kernel(
    const float* __restrict__ logits, const int* __restrict__ tgt,
    float* __restrict__ nll)
{
    __shared__ float red[256];
    int row = blockIdx.x;
    int tid = threadIdx.x;
    const float* lr = logits + (size_t)row * VV;

    float mx = -3.4e38f;
    for (int i = tid; i < VV; i += 256) mx = fmaxf(mx, lr[i]);
    red[tid] = mx; __syncthreads();
    for (int o = 128; o > 0; o >>= 1) {
        if (tid < o) red[tid] = fmaxf(red[tid], red[tid + o]);
        __syncthreads();
    }
    mx = red[0];
    __syncthreads();

    float s = 0.0f;
    for (int i = tid; i < VV; i += 256) s += __expf(lr[i] - mx);
    red[tid] = s; __syncthreads();
    for (int o = 128; o > 0; o >>= 1) {
        if (tid < o) red[tid] += red[tid + o];
        __syncthreads();
    }
    if (tid == 0) {
        float lse = mx + logf(red[0]);
        int tg = tgt[row];
        nll[row] = (tg != 0) ? (lse - lr[tg]) : 0.0f;
    }
}

__global__ __launch_bounds__(256) void loss_kernel(
    const float* __restrict__ nll, const int* __restrict__ tgt,
    float* __restrict__ out)
{
    __shared__ float s[256];
    __shared__ float c[256];
    int tid = threadIdx.x;
    float sv = 0.0f, cv = 0.0f;
    for (int i = tid; i < ROWS; i += 256) {
        sv += nll[i];
        cv += (tgt[i] != 0) ? 1.0f : 0.0f;
    }
    s[tid] = sv; c[tid] = cv; __syncthreads();
    for (int o = 128; o > 0; o >>= 1) {
        if (tid < o) { s[tid] += s[tid+o]; c[tid] += c[tid+o]; }
        __syncthreads();
    }
    if (tid == 0) out[0] = s[0] / fmaxf(c[0], 1.0f);
}

// ---------------------------------------------------------------------------
// Launcher
// ---------------------------------------------------------------------------
extern "C" void kernel_launch(void* const* d_in, const int* in_sizes, int n_in,
                              void* d_out, int out_size)
{
    const int*   idx   = (const int*)  d_in[0];
    const int*   tgt   = (const int*)  d_in[1];
    const float* tok   = (const float*)d_in[2];
    const float* pos   = (const float*)d_in[3];
    const float* ln1g  = (const float*)d_in[4];
    const float* ln1b  = (const float*)d_in[5];
    const float* wqkv  = (const float*)d_in[6];
    const float* bqkv  = (const float*)d_in[7];
    const float* wproj = (const float*)d_in[8];
    const float* bproj = (const float*)d_in[9];
    const float* ln2g  = (const float*)d_in[10];
    const float* ln2b  = (const float*)d_in[11];
    const float* w1    = (const float*)d_in[12];
    const float* b1    = (const float*)d_in[13];
    const float* w2    = (const float*)d_in[14];
    const float* b2    = (const float*)d_in[15];
    const float* lmw   = (const float*)d_in[16];

    float *px, *ph, *pqkv, *py, *pm, *pnll;
    float *pwqkvT, *pwprojT, *pw1T, *pw2T, *plmwT;
    cudaGetSymbolAddress((void**)&px,     g_x);
    cudaGetSymbolAddress((void**)&ph,     g_h);
    cudaGetSymbolAddress((void**)&pqkv,   g_qkv);
    cudaGetSymbolAddress((void**)&py,     g_y);
    cudaGetSymbolAddress((void**)&pm,     g_m);
    cudaGetSymbolAddress((void**)&pnll,   g_nll);
    cudaGetSymbolAddress((void**)&pwqkvT, g_wqkvT);
    cudaGetSymbolAddress((void**)&pwprojT,g_wprojT);
    cudaGetSymbolAddress((void**)&pw1T,   g_w1T);
    cudaGetSymbolAddress((void**)&pw2T,   g_w2T);
    cudaGetSymbolAddress((void**)&plmwT,  g_lmwT);

    cudaFuncSetAttribute((const void*)hgemm_kernel<0>,
                         cudaFuncAttributeMaxDynamicSharedMemorySize, SMEM_DYN);
    cudaFuncSetAttribute((const void*)hgemm_kernel<1>,
                         cudaFuncAttributeMaxDynamicSharedMemorySize, SMEM_DYN);
    cudaFuncSetAttribute((const void*)hgemm_kernel<2>,
                         cudaFuncAttributeMaxDynamicSharedMemorySize, SMEM_DYN);

    float* out = (float*)d_out;

    // weight transposes (graph-captured each launch)
    tp_kernel<<<dim3(3*DD/32, DD/32, LL), 256>>>(
        wqkv, pwqkvT, DD, 3*DD, 3*DD, (size_t)DD*3*DD, (size_t)3*DD*DD);
    tp_kernel<<<dim3(DD/32, DD/32, LL), 256>>>(
        wproj, pwprojT, DD, DD, DD, (size_t)DD*DD, (size_t)DD*DD);
    tp_kernel<<<dim3(4*DD/32, DD/32, LL), 256>>>(
        w1, pw1T, DD, 4*DD, 4*DD, (size_t)DD*4*DD, (size_t)4*DD*DD);
    tp_kernel<<<dim3(DD/32, 4*DD/32, LL), 256>>>(
        w2, pw2T, 4*DD, DD, DD, (size_t)4*DD*DD, (size_t)DD*4*DD);
    tp_kernel<<<dim3(VPAD/32, DD/32, 1), 256>>>(
        lmw, plmwT, DD, VV, VPAD, 0, 0);

    embed_kernel<<<ROWS, 256>>>(idx, tok, pos, px);

    for (int l = 0; l < LL; l++) {
        ln_kernel<<<ROWS, 256>>>(px, ln1g + (size_t)l*DD, ln1b + (size_t)l*DD, ph);
        hgemm_kernel<0><<<dim3(3*DD/128, ROWS/128), 256, SMEM_DYN>>>(
            ROWS, 3*DD, DD, ph, pwqkvT + (size_t)l*3*DD*DD,
            bqkv + (size_t)l*3*DD, nullptr, pqkv);
        attn_kernel<<<dim3(BB*HH, TT/128), 128>>>(pqkv, py);
        hgemm_kernel<2><<<dim3(DD/128, ROWS/128), 256, SMEM_DYN>>>(
            ROWS, DD, DD, py, pwprojT + (size_t)l*DD*DD,
            bproj + (size_t)l*DD, px, px);
        ln_kernel<<<ROWS, 256>>>(px, ln2g + (size_t)l*DD, ln2b + (size_t)l*DD, ph);
        hgemm_kernel<1><<<dim3(4*DD/128, ROWS/128), 256, SMEM_DYN>>>(
            ROWS, 4*DD, DD, ph, pw1T + (size_t)l*4*DD*DD,
            b1 + (size_t)l*4*DD, nullptr, pm);
        hgemm_kernel<2><<<dim3(DD/128, ROWS/128), 256, SMEM_DYN>>>(
            ROWS, DD, 4*DD, pm, pw2T + (size_t)l*DD*4*DD,
            b2 + (size_t)l*DD, px, px);
    }

    // logits = x @ lm_w
    hgemm_kernel<0><<<dim3(VPAD/128, ROWS/128), 256, SMEM_DYN>>>(
        ROWS, VV, DD, px, plmwT, nullptr, nullptr, out);

    // loss
    nll_kernel<<<ROWS, 256>>>(out, tgt, pnll);
    size_t nlog = (size_t)ROWS * VV;
    if ((size_t)out_size > nlog) {
        loss_kernel<<<1, 256>>>(pnll, tgt, out + nlog);
    }
}